// round 1
// baseline (speedup 1.0000x reference)
#include <cuda_runtime.h>
#include <cstdint>

// Fused: per-graph input segment-sum -> mean -> [1,128]@[128,256]+bias.
// Exploits linearity: mean(xW+b) = mean(x)W + b (count>0), else 0.
//
// Inputs (metadata order):
//  0: x_a  [524288,128] f32
//  1: W_a  [128,256]    f32
//  2: b_a  [256]        f32
//  3: x_b  [524288,128] f32
//  4: W_b  [128,256]    f32
//  5: b_b  [256]        f32
//  6: ptr_a [4097] i32
//  7: ptr_b [4097] i32
// Output: [4096, 512] f32  (cols 0..255 = type a, 256..511 = type b)

#define D_IN 128
#define D_OUT 256
#define NGRAPH 4096

__global__ __launch_bounds__(256, 8)
void seg_mean_linear_kernel(const float* __restrict__ x,
                            const float* __restrict__ W,
                            const float* __restrict__ bias,
                            const int*   __restrict__ ptr,
                            float*       __restrict__ out,
                            int col_off)
{
    const int g   = blockIdx.x;
    const int tid = threadIdx.x;            // 256 threads = 8 warps
    const int w   = tid >> 5;               // warp id 0..7
    const int c4  = tid & 31;               // float4 column 0..31

    const int r0 = ptr[g];
    const int r1 = ptr[g + 1];
    const int cnt = r1 - r0;

    // ---- Phase 1: segment sum of x rows [r0, r1) over 128 columns ----
    const float4* __restrict__ x4 = reinterpret_cast<const float4*>(x);

    float4 a0 = make_float4(0.f, 0.f, 0.f, 0.f);
    float4 a1 = make_float4(0.f, 0.f, 0.f, 0.f);

    int i = r0 + w;                          // each warp strides 8 rows
    for (; i + 8 < r1; i += 16) {
        float4 v0 = __ldg(&x4[(size_t)i * 32 + c4]);
        float4 v1 = __ldg(&x4[(size_t)(i + 8) * 32 + c4]);
        a0.x += v0.x; a0.y += v0.y; a0.z += v0.z; a0.w += v0.w;
        a1.x += v1.x; a1.y += v1.y; a1.z += v1.z; a1.w += v1.w;
    }
    if (i < r1) {
        float4 v0 = __ldg(&x4[(size_t)i * 32 + c4]);
        a0.x += v0.x; a0.y += v0.y; a0.z += v0.z; a0.w += v0.w;
    }
    a0.x += a1.x; a0.y += a1.y; a0.z += a1.z; a0.w += a1.w;

    __shared__ float red[8][D_IN];           // per-warp partial sums
    __shared__ float mean_s[D_IN];

    red[w][c4 * 4 + 0] = a0.x;
    red[w][c4 * 4 + 1] = a0.y;
    red[w][c4 * 4 + 2] = a0.z;
    red[w][c4 * 4 + 3] = a0.w;
    __syncthreads();

    if (tid < D_IN) {
        float s = 0.f;
        #pragma unroll
        for (int ww = 0; ww < 8; ww++) s += red[ww][tid];
        mean_s[tid] = (cnt > 0) ? s / (float)cnt : 0.f;
    }
    __syncthreads();

    // ---- Phase 2: out[g, col_off + j] = mean . W[:,j] + b[j]  (j = tid) ----
    float o = 0.f;
    if (cnt > 0) {
        float acc = 0.f;
        #pragma unroll 16
        for (int k = 0; k < D_IN; k++) {
            acc += mean_s[k] * __ldg(&W[k * D_OUT + tid]);
        }
        o = acc + __ldg(&bias[tid]);
    }
    out[(size_t)g * (2 * D_OUT) + col_off + tid] = o;
}

extern "C" void kernel_launch(void* const* d_in, const int* in_sizes, int n_in,
                              void* d_out, int out_size)
{
    const float* x_a  = (const float*)d_in[0];
    const float* W_a  = (const float*)d_in[1];
    const float* b_a  = (const float*)d_in[2];
    const float* x_b  = (const float*)d_in[3];
    const float* W_b  = (const float*)d_in[4];
    const float* b_b  = (const float*)d_in[5];
    const int*   ptr_a = (const int*)d_in[6];
    const int*   ptr_b = (const int*)d_in[7];
    float* out = (float*)d_out;

    dim3 grid(NGRAPH);
    dim3 block(256);
    seg_mean_linear_kernel<<<grid, block>>>(x_a, W_a, b_a, ptr_a, out, 0);
    seg_mean_linear_kernel<<<grid, block>>>(x_b, W_b, b_b, ptr_b, out, D_OUT);
}

// round 4
// speedup vs baseline: 1.1934x; 1.1934x over previous
#include <cuda_runtime.h>
#include <cstdint>

// Two-phase:
//  K1: per-(type,graph) CTA streams x rows, writes segment MEAN to g_mean (4 MB scratch).
//  K2: tiled GEMM [8192,128]@[128,256]+bias with W staged in smem once per 64-graph tile,
//      packed f32x2 FMA, empty graphs masked to 0.
//
// Inputs: 0:x_a 1:W_a 2:b_a 3:x_b 4:W_b 5:b_b 6:ptr_a 7:ptr_b
// Output: [4096, 512] f32 (cols 0..255 type a, 256..511 type b)

#define NGRAPH 4096
#define D_IN   128
#define D_OUT  256
#define TM     64   // graphs per GEMM tile

__device__ float g_mean[2 * NGRAPH * D_IN];   // 4 MB scratch

// ---------------- Kernel 1: segment mean ----------------
__global__ __launch_bounds__(128, 8)
void seg_mean_kernel(const float* __restrict__ x_a, const float* __restrict__ x_b,
                     const int* __restrict__ ptr_a, const int* __restrict__ ptr_b)
{
    const int gid = blockIdx.x;               // 0..8191
    const int t   = gid >> 12;                // type
    const int g   = gid & (NGRAPH - 1);

    const float* __restrict__ x   = t ? x_b   : x_a;
    const int*   __restrict__ ptr = t ? ptr_b : ptr_a;

    const int tid = threadIdx.x;              // 128 threads = 4 warps
    const int w   = tid >> 5;                 // warp 0..3
    const int c4  = tid & 31;                 // float4 lane

    const int r0  = ptr[g];
    const int r1  = ptr[g + 1];
    const int cnt = r1 - r0;

    const float4* __restrict__ x4 = reinterpret_cast<const float4*>(x);

    float4 a0 = make_float4(0.f, 0.f, 0.f, 0.f);
    float4 a1 = make_float4(0.f, 0.f, 0.f, 0.f);

    int i = r0 + w;                            // warps stride 4 rows, unroll 2
    for (; i + 4 < r1; i += 8) {
        float4 v0 = __ldg(&x4[(size_t)i * 32 + c4]);
        float4 v1 = __ldg(&x4[(size_t)(i + 4) * 32 + c4]);
        a0.x += v0.x; a0.y += v0.y; a0.z += v0.z; a0.w += v0.w;
        a1.x += v1.x; a1.y += v1.y; a1.z += v1.z; a1.w += v1.w;
    }
    if (i < r1) {
        float4 v0 = __ldg(&x4[(size_t)i * 32 + c4]);
        a0.x += v0.x; a0.y += v0.y; a0.z += v0.z; a0.w += v0.w;
    }
    a0.x += a1.x; a0.y += a1.y; a0.z += a1.z; a0.w += a1.w;

    __shared__ float red[4][D_IN];
    red[w][c4 * 4 + 0] = a0.x;
    red[w][c4 * 4 + 1] = a0.y;
    red[w][c4 * 4 + 2] = a0.z;
    red[w][c4 * 4 + 3] = a0.w;
    __syncthreads();

    // all 128 threads: sum 4 warp-partials for one column
    float s = red[0][tid] + red[1][tid] + red[2][tid] + red[3][tid];
    g_mean[((size_t)t * NGRAPH + g) * D_IN + tid] = (cnt > 0) ? s / (float)cnt : 0.f;
}

// ---------------- Kernel 2: tiled GEMM + bias ----------------
__global__ __launch_bounds__(256, 1)
void gemm_kernel(const float* __restrict__ W_a, const float* __restrict__ b_a,
                 const float* __restrict__ W_b, const float* __restrict__ b_b,
                 const int* __restrict__ ptr_a, const int* __restrict__ ptr_b,
                 float* __restrict__ out)
{
    const int t  = blockIdx.y;
    const int g0 = blockIdx.x * TM;

    const float* __restrict__ W    = t ? W_b   : W_a;
    const float* __restrict__ bias = t ? b_b   : b_a;
    const int*   __restrict__ ptr  = t ? ptr_b : ptr_a;

    __shared__ float meanS[TM][D_IN];      // 32 KB
    __shared__ float WS[32][D_OUT];        // 32 KB (one K-chunk of W)

    const int tid = threadIdx.x;           // 256 = 64 x 4
    const int tx  = tid & 63;              // cols [4*tx, 4*tx+4)
    const int ty  = tid >> 6;              // graph group: m = ty*16 + i

    // load 64x128 mean tile (2048 float4, 8 per thread, coalesced)
    {
        const float4* m4  = reinterpret_cast<const float4*>(g_mean + ((size_t)t * NGRAPH + g0) * D_IN);
        float4*       ms4 = reinterpret_cast<float4*>(&meanS[0][0]);
        #pragma unroll
        for (int j = 0; j < 8; j++) ms4[tid + 256 * j] = m4[tid + 256 * j];
    }

    unsigned long long acc[16][2];         // 16 graphs x 4 cols as 2x f32x2
    #pragma unroll
    for (int i = 0; i < 16; i++) { acc[i][0] = 0ull; acc[i][1] = 0ull; }

    const float4* W4 = reinterpret_cast<const float4*>(W);

    for (int kc = 0; kc < 4; kc++) {
        __syncthreads();                   // protect WS before overwrite
        float4* ws4 = reinterpret_cast<float4*>(&WS[0][0]);
        #pragma unroll
        for (int j = 0; j < 8; j++)
            ws4[tid + 256 * j] = __ldg(&W4[kc * 2048 + tid + 256 * j]);
        __syncthreads();

        #pragma unroll
        for (int k = 0; k < 32; k++) {
            // 4 consecutive W cols for this thread, already bit-packed as 2x f32x2
            ulonglong2 wp = *reinterpret_cast<const ulonglong2*>(&WS[k][4 * tx]);
            #pragma unroll
            for (int i = 0; i < 16; i++) {
                float mv = meanS[ty * 16 + i][kc * 32 + k];   // warp-broadcast LDS
                unsigned long long mm;
                asm("mov.b64 %0, {%1, %1};" : "=l"(mm) : "f"(mv));
                asm("fma.rn.f32x2 %0, %1, %2, %0;" : "+l"(acc[i][0]) : "l"(mm), "l"(wp.x));
                asm("fma.rn.f32x2 %0, %1, %2, %0;" : "+l"(acc[i][1]) : "l"(mm), "l"(wp.y));
            }
        }
    }

    const float4 bv = __ldg(reinterpret_cast<const float4*>(bias) + tx);
    float4* out4 = reinterpret_cast<float4*>(out);

    #pragma unroll
    for (int i = 0; i < 16; i++) {
        const int m   = g0 + ty * 16 + i;
        const int cnt = ptr[m + 1] - ptr[m];
        float4 o;
        asm("mov.b64 {%0, %1}, %2;" : "=f"(o.x), "=f"(o.y) : "l"(acc[i][0]));
        asm("mov.b64 {%0, %1}, %2;" : "=f"(o.z), "=f"(o.w) : "l"(acc[i][1]));
        if (cnt > 0) {
            o.x += bv.x; o.y += bv.y; o.z += bv.z; o.w += bv.w;
        } else {
            o = make_float4(0.f, 0.f, 0.f, 0.f);
        }
        // out row m, cols t*256 + 4*tx : float4 index m*128 + t*64 + tx
        out4[(size_t)m * 128 + t * 64 + tx] = o;
    }
}

extern "C" void kernel_launch(void* const* d_in, const int* in_sizes, int n_in,
                              void* d_out, int out_size)
{
    const float* x_a   = (const float*)d_in[0];
    const float* W_a   = (const float*)d_in[1];
    const float* b_a   = (const float*)d_in[2];
    const float* x_b   = (const float*)d_in[3];
    const float* W_b   = (const float*)d_in[4];
    const float* b_b   = (const float*)d_in[5];
    const int*   ptr_a = (const int*)d_in[6];
    const int*   ptr_b = (const int*)d_in[7];
    float* out = (float*)d_out;

    seg_mean_kernel<<<2 * NGRAPH, 128>>>(x_a, x_b, ptr_a, ptr_b);

    dim3 gridB(NGRAPH / TM, 2);
    gemm_kernel<<<gridB, 256>>>(W_a, b_a, W_b, b_b, ptr_a, ptr_b, out);
}

// round 9
// speedup vs baseline: 1.2312x; 1.0317x over previous
#include <cuda_runtime.h>
#include <cstdint>

// K1: per-(half,type,graph) CTA streams half a graph's rows -> partial SUM in g_part (8 MB).
// K2: tiled GEMM: mean = (p0+p1)/cnt, [32,128]@[128,256]+bias, W staged in smem, f32x2 FMA.
//
// Inputs: 0:x_a 1:W_a 2:b_a 3:x_b 4:W_b 5:b_b 6:ptr_a 7:ptr_b
// Output: [4096, 512] f32 (cols 0..255 type a, 256..511 type b)

#define NGRAPH 4096
#define D_IN   128
#define D_OUT  256
#define TM     32    // graphs per GEMM tile

// layout: plane (h*2 + t), then graph, then col
__device__ float g_part[4 * NGRAPH * D_IN];   // 8 MB scratch

// ---------------- Kernel 1: half-graph partial sums ----------------
__global__ __launch_bounds__(128, 8)
void seg_sum_kernel(const float* __restrict__ x_a, const float* __restrict__ x_b,
                    const int* __restrict__ ptr_a, const int* __restrict__ ptr_b)
{
    const int bid = blockIdx.x;               // 0..16383
    const int h   = bid >> 13;                // half
    const int t   = (bid >> 12) & 1;          // type
    const int g   = bid & (NGRAPH - 1);

    const float* __restrict__ x   = t ? x_b   : x_a;
    const int*   __restrict__ ptr = t ? ptr_b : ptr_a;

    const int tid = threadIdx.x;              // 128 = 4 warps
    const int w   = tid >> 5;
    const int c4  = tid & 31;

    const int r0  = ptr[g];
    const int r1  = ptr[g + 1];
    const int mid = r0 + ((r1 - r0) >> 1);
    const int rs  = h ? mid : r0;
    const int re  = h ? r1  : mid;

    const float4* __restrict__ x4 = reinterpret_cast<const float4*>(x);

    float4 a0 = make_float4(0.f,0.f,0.f,0.f);
    float4 a1 = make_float4(0.f,0.f,0.f,0.f);
    float4 a2 = make_float4(0.f,0.f,0.f,0.f);
    float4 a3 = make_float4(0.f,0.f,0.f,0.f);

    int i = rs + w;                           // each warp owns one row per step of 4
    for (; i + 12 < re; i += 16) {            // 4 rows in flight per warp
        float4 v0 = __ldg(&x4[(size_t)i        * 32 + c4]);
        float4 v1 = __ldg(&x4[(size_t)(i + 4)  * 32 + c4]);
        float4 v2 = __ldg(&x4[(size_t)(i + 8)  * 32 + c4]);
        float4 v3 = __ldg(&x4[(size_t)(i + 12) * 32 + c4]);
        a0.x += v0.x; a0.y += v0.y; a0.z += v0.z; a0.w += v0.w;
        a1.x += v1.x; a1.y += v1.y; a1.z += v1.z; a1.w += v1.w;
        a2.x += v2.x; a2.y += v2.y; a2.z += v2.z; a2.w += v2.w;
        a3.x += v3.x; a3.y += v3.y; a3.z += v3.z; a3.w += v3.w;
    }
    for (; i < re; i += 4) {
        float4 v0 = __ldg(&x4[(size_t)i * 32 + c4]);
        a0.x += v0.x; a0.y += v0.y; a0.z += v0.z; a0.w += v0.w;
    }
    a0.x += a1.x + a2.x + a3.x;
    a0.y += a1.y + a2.y + a3.y;
    a0.z += a1.z + a2.z + a3.z;
    a0.w += a1.w + a2.w + a3.w;

    __shared__ float red[4][D_IN];
    red[w][c4 * 4 + 0] = a0.x;
    red[w][c4 * 4 + 1] = a0.y;
    red[w][c4 * 4 + 2] = a0.z;
    red[w][c4 * 4 + 3] = a0.w;
    __syncthreads();

    float s = red[0][tid] + red[1][tid] + red[2][tid] + red[3][tid];
    g_part[(((size_t)h * 2 + t) * NGRAPH + g) * D_IN + tid] = s;
}

// ---------------- Kernel 2: combine + GEMM + bias ----------------
__global__ __launch_bounds__(256, 2)
void gemm_kernel(const float* __restrict__ W_a, const float* __restrict__ b_a,
                 const float* __restrict__ W_b, const float* __restrict__ b_b,
                 const int* __restrict__ ptr_a, const int* __restrict__ ptr_b,
                 float* __restrict__ out)
{
    const int t  = blockIdx.y;
    const int g0 = blockIdx.x * TM;

    const float* __restrict__ W    = t ? W_b   : W_a;
    const float* __restrict__ bias = t ? b_b   : b_a;
    const int*   __restrict__ ptr  = t ? ptr_b : ptr_a;

    __shared__ float meanS[TM][D_IN];      // 16 KB
    __shared__ float WS[32][D_OUT];        // 32 KB (one K-chunk of W)
    __shared__ float invc[TM];

    const int tid = threadIdx.x;           // 256 = 64 x 4
    const int tx  = tid & 63;              // cols [4*tx, 4*tx+4)
    const int ty  = tid >> 6;              // graphs ty*8 .. ty*8+7

    if (tid < TM) {
        int m = g0 + tid;
        int c = ptr[m + 1] - ptr[m];
        invc[tid] = (c > 0) ? 1.f / (float)c : 0.f;
    }
    __syncthreads();

    // combine halves -> mean tile (32x128 = 1024 float4, 4 per thread)
    {
        const float4* p0 = reinterpret_cast<const float4*>(
            g_part + ((size_t)t * NGRAPH + g0) * D_IN);
        const float4* p1 = reinterpret_cast<const float4*>(
            g_part + (((size_t)2 + t) * NGRAPH + g0) * D_IN);
        #pragma unroll
        for (int j = 0; j < 4; j++) {
            int idx = tid + 256 * j;
            int row = idx >> 5;
            float4 u = p0[idx];
            float4 v = p1[idx];
            float  r = invc[row];
            float4 m;
            m.x = (u.x + v.x) * r;
            m.y = (u.y + v.y) * r;
            m.z = (u.z + v.z) * r;
            m.w = (u.w + v.w) * r;
            reinterpret_cast<float4*>(&meanS[0][0])[idx] = m;
        }
    }

    unsigned long long acc[8][2];          // 8 graphs x 4 cols as 2x f32x2
    #pragma unroll
    for (int i = 0; i < 8; i++) { acc[i][0] = 0ull; acc[i][1] = 0ull; }

    const float4* W4 = reinterpret_cast<const float4*>(W);

    for (int kc = 0; kc < 4; kc++) {
        __syncthreads();                   // protect WS before overwrite (also covers meanS fill on kc=0)
        float4* ws4 = reinterpret_cast<float4*>(&WS[0][0]);
        #pragma unroll
        for (int j = 0; j < 8; j++)
            ws4[tid + 256 * j] = __ldg(&W4[kc * 2048 + tid + 256 * j]);
        __syncthreads();

        #pragma unroll
        for (int k = 0; k < 32; k++) {
            ulonglong2 wp = *reinterpret_cast<const ulonglong2*>(&WS[k][4 * tx]);
            #pragma unroll
            for (int i = 0; i < 8; i++) {
                float mv = meanS[ty * 8 + i][kc * 32 + k];   // warp-broadcast LDS
                unsigned long long mm;
                asm("mov.b64 %0, {%1, %1};" : "=l"(mm) : "f"(mv));
                asm("fma.rn.f32x2 %0, %1, %2, %0;" : "+l"(acc[i][0]) : "l"(mm), "l"(wp.x));
                asm("fma.rn.f32x2 %0, %1, %2, %0;" : "+l"(acc[i][1]) : "l"(mm), "l"(wp.y));
            }
        }
    }

    const float4 bv = __ldg(reinterpret_cast<const float4*>(bias) + tx);
    float4* out4 = reinterpret_cast<float4*>(out);

    #pragma unroll
    for (int i = 0; i < 8; i++) {
        const int ml = ty * 8 + i;
        const int m  = g0 + ml;
        float4 o;
        asm("mov.b64 {%0, %1}, %2;" : "=f"(o.x), "=f"(o.y) : "l"(acc[i][0]));
        asm("mov.b64 {%0, %1}, %2;" : "=f"(o.z), "=f"(o.w) : "l"(acc[i][1]));
        if (invc[ml] > 0.f) {
            o.x += bv.x; o.y += bv.y; o.z += bv.z; o.w += bv.w;
        } else {
            o = make_float4(0.f, 0.f, 0.f, 0.f);
        }
        out4[(size_t)m * 128 + t * 64 + tx] = o;
    }
}

extern "C" void kernel_launch(void* const* d_in, const int* in_sizes, int n_in,
                              void* d_out, int out_size)
{
    const float* x_a   = (const float*)d_in[0];
    const float* W_a   = (const float*)d_in[1];
    const float* b_a   = (const float*)d_in[2];
    const float* x_b   = (const float*)d_in[3];
    const float* W_b   = (const float*)d_in[4];
    const float* b_b   = (const float*)d_in[5];
    const int*   ptr_a = (const int*)d_in[6];
    const int*   ptr_b = (const int*)d_in[7];
    float* out = (float*)d_out;

    seg_sum_kernel<<<4 * NGRAPH, 128>>>(x_a, x_b, ptr_a, ptr_b);

    dim3 gridB(NGRAPH / TM, 2);
    gemm_kernel<<<gridB, 256>>>(W_a, b_a, W_b, b_b, ptr_a, ptr_b, out);
}